// round 11
// baseline (speedup 1.0000x reference)
#include <cuda_runtime.h>

// Problem constants
#define DD 160
#define HH 192
#define WW 160
#define DHW (DD*HH*WW)          // 4,915,200 (divisible by 4 -> channel planes stay 16B aligned)
#define BB 2
#define CC 2

__device__ __forceinline__ float pick4(const float4& v, int sel) {
    // dynamic element select from float4 without local memory
    float lo = (sel & 2) ? v.z : v.x;
    float hi = (sel & 2) ? v.w : v.y;
    return (sel & 1) ? hi : lo;
}

__global__ __launch_bounds__(256)
void warp3d_kernel(const float* __restrict__ x,
                   const float* __restrict__ flow,
                   float* __restrict__ out)
{
    int idx = blockIdx.x * blockDim.x + threadIdx.x;
    if (idx >= BB * DHW) return;

    int b = idx / DHW;
    int s = idx - b * DHW;
    int xw = s % WW;
    int t  = s / WW;
    int yh = t % HH;
    int zd = t / HH;

    const float* fb = flow + (size_t)b * 3 * DHW;
    float pz = (float)zd + fb[s];
    float py = (float)yh + fb[s + DHW];
    float px = (float)xw + fb[s + 2 * DHW];

    float z0f = floorf(pz), y0f = floorf(py), x0f = floorf(px);
    float fz = pz - z0f, fy = py - y0f, fx = px - x0f;
    int z0 = (int)z0f, y0 = (int)y0f, x0 = (int)x0f;
    int z1 = z0 + 1, y1 = y0 + 1, x1 = x0 + 1;

    // per-axis weights, zeroed when the corner index is out of bounds
    float wz0 = (z0 >= 0 && z0 < DD) ? (1.0f - fz) : 0.0f;
    float wz1 = (z1 >= 0 && z1 < DD) ? fz          : 0.0f;
    float wy0 = (y0 >= 0 && y0 < HH) ? (1.0f - fy) : 0.0f;
    float wy1 = (y1 >= 0 && y1 < HH) ? fy          : 0.0f;
    float wx0 = (x0 >= 0 && x0 < WW) ? (1.0f - fx) : 0.0f;
    float wx1 = (x1 >= 0 && x1 < WW) ? fx          : 0.0f;

    // clamped indices
    int zc0 = min(max(z0, 0), DD - 1);
    int zc1 = min(max(z1, 0), DD - 1);
    int yc0 = min(max(y0, 0), HH - 1);
    int yc1 = min(max(y1, 0), HH - 1);
    int xc0 = min(max(x0, 0), WW - 1);
    int xc1 = min(max(x1, 0), WW - 1);

    // x-pair vector-load plan (shared by all 4 row-groups: row bases are
    // multiples of WW=160, i.e. 16B-aligned, so sel depends only on xc0)
    int axc0 = xc0 & ~3;          // aligned float4 start within the row
    int sel  = xc0 & 3;           // position of xc0 inside the float4
    int dxc  = xc1 - xc0;         // 0 (clamped equal) or 1
    bool extra = (sel == 3) && (dxc == 1);   // xc1 falls outside the float4
    int sel1 = extra ? 3 : (sel + dxc);      // select for xc1 when no extra load

    // row-group weights (z,y combined)
    float wzy00 = wz0 * wy0;
    float wzy01 = wz0 * wy1;
    float wzy10 = wz1 * wy0;
    float wzy11 = wz1 * wy1;

    int base00 = (zc0 * HH + yc0) * WW + axc0;
    int base01 = (zc0 * HH + yc1) * WW + axc0;
    int base10 = (zc1 * HH + yc0) * WW + axc0;
    int base11 = (zc1 * HH + yc1) * WW + axc0;

    const float* xb0 = x + (size_t)b * CC * DHW;   // channel 0
    const float* xb1 = xb0 + DHW;                  // channel 1

    float a0 = 0.0f, a1 = 0.0f;

    #define ROWGROUP(BASE, WZY)                                              \
    {                                                                        \
        float4 v0 = __ldg((const float4*)(xb0 + (BASE)));                    \
        float4 v1 = __ldg((const float4*)(xb1 + (BASE)));                    \
        float e00 = pick4(v0, sel);                                          \
        float e10 = pick4(v1, sel);                                          \
        float e01, e11;                                                      \
        if (extra) {                                                         \
            e01 = __ldg(xb0 + (BASE) + 4);                                   \
            e11 = __ldg(xb1 + (BASE) + 4);                                   \
        } else {                                                             \
            e01 = pick4(v0, sel1);                                           \
            e11 = pick4(v1, sel1);                                           \
        }                                                                    \
        a0 = fmaf((WZY), fmaf(e00, wx0, e01 * wx1), a0);                     \
        a1 = fmaf((WZY), fmaf(e10, wx0, e11 * wx1), a1);                     \
    }

    ROWGROUP(base00, wzy00)
    ROWGROUP(base01, wzy01)
    ROWGROUP(base10, wzy10)
    ROWGROUP(base11, wzy11)

    #undef ROWGROUP

    float* ob = out + (size_t)b * CC * DHW;
    ob[s]       = a0;
    ob[s + DHW] = a1;
}

extern "C" void kernel_launch(void* const* d_in, const int* in_sizes, int n_in,
                              void* d_out, int out_size)
{
    const float* x    = (const float*)d_in[0];
    const float* flow = (const float*)d_in[1];
    float* out        = (float*)d_out;

    const int N = BB * DHW;
    const int threads = 256;
    const int blocks = (N + threads - 1) / threads;
    warp3d_kernel<<<blocks, threads>>>(x, flow, out);
}

// round 12
// speedup vs baseline: 1.1950x; 1.1950x over previous
#include <cuda_runtime.h>

// Problem constants
#define DD 160
#define HH 192
#define WW 160
#define DHW (DD*HH*WW)          // 4,915,200
#define BB 2

// Tiling
#define TX 32
#define TY 8
#define TZ 8
#define HALO 4
#define RX (TX + 2*HALO)        // 40
#define RY (TY + 2*HALO)        // 16
#define RZ (TZ + 2*HALO)        // 16
#define NTHREADS 512
#define SMEM_BYTES (RX*RY*RZ*sizeof(float2))   // 81920 B

__global__ __launch_bounds__(NTHREADS, 2)
void warp3d_tiled(const float* __restrict__ x,
                  const float* __restrict__ flow,
                  float* __restrict__ out)
{
    extern __shared__ float2 sreg[];   // [RZ][RY][RX], channels interleaved

    // decode block -> (tile_x, tile_y, tile_z, batch)
    int bidx = blockIdx.x;
    int txi = bidx % (WW/TX); bidx /= (WW/TX);
    int tyi = bidx % (HH/TY); bidx /= (HH/TY);
    int tzi = bidx % (DD/TZ); bidx /= (DD/TZ);
    int b   = bidx;

    int tx0 = txi*TX, ty0 = tyi*TY, tz0 = tzi*TZ;
    int wx0 = tx0 - HALO, wy0 = ty0 - HALO, wz0 = tz0 - HALO;

    const float* __restrict__ xb0 = x + (size_t)b * 2 * DHW;   // channel 0
    const float* __restrict__ xb1 = xb0 + DHW;                 // channel 1

    // ---- stage halo region into shared memory (channel-interleaved) ----
    for (int i = threadIdx.x; i < RZ*RY*RX; i += NTHREADS) {
        int rx = i % RX;
        int rt = i / RX;
        int ry = rt % RY;
        int rz = rt / RY;
        int gx = wx0 + rx, gy = wy0 + ry, gz = wz0 + rz;
        if ((unsigned)gx < WW && (unsigned)gy < HH && (unsigned)gz < DD) {
            int g = (gz*HH + gy)*WW + gx;
            sreg[i] = make_float2(__ldg(xb0 + g), __ldg(xb1 + g));
        }
        // cells outside the volume stay garbage — clamped indices never hit them
    }
    __syncthreads();

    // thread -> voxel mapping: lanes contiguous in x (coalesced flow/out)
    int lx = threadIdx.x & (TX-1);          // 0..31
    int ly = (threadIdx.x >> 5) & (TY-1);   // 0..7
    int lzh = threadIdx.x >> 8;             // 0..1

    int xw = tx0 + lx;
    int yh = ty0 + ly;

    const float* __restrict__ fb = flow + (size_t)b * 3 * DHW;
    float*       __restrict__ ob = out  + (size_t)b * 2 * DHW;

#pragma unroll
    for (int k = 0; k < TZ/2; k++) {
        int zd = tz0 + lzh*(TZ/2) + k;
        int s = (zd*HH + yh)*WW + xw;

        float pz = (float)zd + __ldg(fb + s);
        float py = (float)yh + __ldg(fb + s + DHW);
        float px = (float)xw + __ldg(fb + s + 2*DHW);

        float z0f = floorf(pz), y0f = floorf(py), x0f = floorf(px);
        float fz = pz - z0f, fy = py - y0f, fx = px - x0f;
        int z0 = (int)z0f, y0 = (int)y0f, x0 = (int)x0f;
        int z1 = z0 + 1, y1 = y0 + 1, x1 = x0 + 1;

        // per-axis weights, zeroed when the (unclamped) corner is OOB
        float wz0w = (z0 >= 0 && z0 < DD) ? (1.0f - fz) : 0.0f;
        float wz1w = (z1 >= 0 && z1 < DD) ? fz          : 0.0f;
        float wy0w = (y0 >= 0 && y0 < HH) ? (1.0f - fy) : 0.0f;
        float wy1w = (y1 >= 0 && y1 < HH) ? fy          : 0.0f;
        float wx0w = (x0 >= 0 && x0 < WW) ? (1.0f - fx) : 0.0f;
        float wx1w = (x1 >= 0 && x1 < WW) ? fx          : 0.0f;

        int zc0 = min(max(z0,0),DD-1), zc1 = min(max(z1,0),DD-1);
        int yc0 = min(max(y0,0),HH-1), yc1 = min(max(y1,0),HH-1);
        int xc0 = min(max(x0,0),WW-1), xc1 = min(max(x1,0),WW-1);

        float w00 = wz0w*wy0w, w01 = wz0w*wy1w;
        float w10 = wz1w*wy0w, w11 = wz1w*wy1w;

        float acc0 = 0.0f, acc1 = 0.0f;

        bool inwin = (zc0 >= wz0) & (zc1 < wz0+RZ) &
                     (yc0 >= wy0) & (yc1 < wy0+RY) &
                     (xc0 >= wx0) & (xc1 < wx0+RX);

        if (inwin) {
            int rz0 = zc0 - wz0, rz1 = zc1 - wz0;
            int ry0 = yc0 - wy0, ry1 = yc1 - wy0;
            int rx0 = xc0 - wx0, rx1 = xc1 - wx0;
            const float2* r00 = sreg + (rz0*RY + ry0)*RX;
            const float2* r01 = sreg + (rz0*RY + ry1)*RX;
            const float2* r10 = sreg + (rz1*RY + ry0)*RX;
            const float2* r11 = sreg + (rz1*RY + ry1)*RX;
            float2 v; float c;
            c = w00*wx0w; v = r00[rx0]; acc0 = fmaf(v.x,c,acc0); acc1 = fmaf(v.y,c,acc1);
            c = w00*wx1w; v = r00[rx1]; acc0 = fmaf(v.x,c,acc0); acc1 = fmaf(v.y,c,acc1);
            c = w01*wx0w; v = r01[rx0]; acc0 = fmaf(v.x,c,acc0); acc1 = fmaf(v.y,c,acc1);
            c = w01*wx1w; v = r01[rx1]; acc0 = fmaf(v.x,c,acc0); acc1 = fmaf(v.y,c,acc1);
            c = w10*wx0w; v = r10[rx0]; acc0 = fmaf(v.x,c,acc0); acc1 = fmaf(v.y,c,acc1);
            c = w10*wx1w; v = r10[rx1]; acc0 = fmaf(v.x,c,acc0); acc1 = fmaf(v.y,c,acc1);
            c = w11*wx0w; v = r11[rx0]; acc0 = fmaf(v.x,c,acc0); acc1 = fmaf(v.y,c,acc1);
            c = w11*wx1w; v = r11[rx1]; acc0 = fmaf(v.x,c,acc0); acc1 = fmaf(v.y,c,acc1);
        } else {
            // rare fallback: exact global gather (same semantics)
            int o00 = (zc0*HH + yc0)*WW, o01 = (zc0*HH + yc1)*WW;
            int o10 = (zc1*HH + yc0)*WW, o11 = (zc1*HH + yc1)*WW;
            float c;
            c = w00*wx0w; acc0 = fmaf(__ldg(xb0+o00+xc0),c,acc0); acc1 = fmaf(__ldg(xb1+o00+xc0),c,acc1);
            c = w00*wx1w; acc0 = fmaf(__ldg(xb0+o00+xc1),c,acc0); acc1 = fmaf(__ldg(xb1+o00+xc1),c,acc1);
            c = w01*wx0w; acc0 = fmaf(__ldg(xb0+o01+xc0),c,acc0); acc1 = fmaf(__ldg(xb1+o01+xc0),c,acc1);
            c = w01*wx1w; acc0 = fmaf(__ldg(xb0+o01+xc1),c,acc0); acc1 = fmaf(__ldg(xb1+o01+xc1),c,acc1);
            c = w10*wx0w; acc0 = fmaf(__ldg(xb0+o10+xc0),c,acc0); acc1 = fmaf(__ldg(xb1+o10+xc0),c,acc1);
            c = w10*wx1w; acc0 = fmaf(__ldg(xb0+o10+xc1),c,acc0); acc1 = fmaf(__ldg(xb1+o10+xc1),c,acc1);
            c = w11*wx0w; acc0 = fmaf(__ldg(xb0+o11+xc0),c,acc0); acc1 = fmaf(__ldg(xb1+o11+xc0),c,acc1);
            c = w11*wx1w; acc0 = fmaf(__ldg(xb0+o11+xc1),c,acc0); acc1 = fmaf(__ldg(xb1+o11+xc1),c,acc1);
        }

        ob[s]       = acc0;
        ob[s + DHW] = acc1;
    }
}

extern "C" void kernel_launch(void* const* d_in, const int* in_sizes, int n_in,
                              void* d_out, int out_size)
{
    const float* x    = (const float*)d_in[0];
    const float* flow = (const float*)d_in[1];
    float* out        = (float*)d_out;

    cudaFuncSetAttribute(warp3d_tiled,
                         cudaFuncAttributeMaxDynamicSharedMemorySize,
                         (int)SMEM_BYTES);

    const int blocks = (WW/TX) * (HH/TY) * (DD/TZ) * BB;   // 4800
    warp3d_tiled<<<blocks, NTHREADS, SMEM_BYTES>>>(x, flow, out);
}

// round 13
// speedup vs baseline: 1.6727x; 1.3997x over previous
#include <cuda_runtime.h>

// Problem constants
#define DD 160
#define HH 192
#define WW 160
#define DHW (DD*HH*WW)          // 4,915,200
#define BB 2

// Channel-interleaved scratch copy of x: [b][z][y][x] -> float2{ch0, ch1}
__device__ float2 g_pair[BB * DHW];

// ---------------------------------------------------------------------------
// Pre-pass: build channel-interleaved copy (fully coalesced, vectorized)
// ---------------------------------------------------------------------------
__global__ __launch_bounds__(256)
void interleave_kernel(const float* __restrict__ x)
{
    int j = blockIdx.x * blockDim.x + threadIdx.x;   // float4 index within a batch
    const int NJ = DHW / 4;
    if (j >= BB * NJ) return;
    int b = j / NJ;
    int jj = j - b * NJ;

    const float4* c0 = (const float4*)(x + (size_t)b * 2 * DHW);
    const float4* c1 = (const float4*)(x + (size_t)b * 2 * DHW + DHW);
    float4 a = __ldg(c0 + jj);
    float4 c = __ldg(c1 + jj);

    float4* dst = (float4*)(g_pair + (size_t)b * DHW);
    dst[2*jj]     = make_float4(a.x, c.x, a.y, c.y);
    dst[2*jj + 1] = make_float4(a.z, c.z, a.w, c.w);
}

// ---------------------------------------------------------------------------
// Main warp kernel: 8 float2 gathers (both channels per gather)
// ---------------------------------------------------------------------------
__global__ __launch_bounds__(256)
void warp3d_kernel(const float* __restrict__ flow,
                   float* __restrict__ out)
{
    int idx = blockIdx.x * blockDim.x + threadIdx.x;
    if (idx >= BB * DHW) return;

    int b = idx / DHW;
    int s = idx - b * DHW;
    int xw = s % WW;
    int t  = s / WW;
    int yh = t % HH;
    int zd = t / HH;

    const float* fb = flow + (size_t)b * 3 * DHW;
    float pz = (float)zd + __ldg(fb + s);
    float py = (float)yh + __ldg(fb + s + DHW);
    float px = (float)xw + __ldg(fb + s + 2 * DHW);

    float z0f = floorf(pz), y0f = floorf(py), x0f = floorf(px);
    float fz = pz - z0f, fy = py - y0f, fx = px - x0f;
    int z0 = (int)z0f, y0 = (int)y0f, x0 = (int)x0f;
    int z1 = z0 + 1, y1 = y0 + 1, x1 = x0 + 1;

    // per-axis weights, zeroed when the corner index is out of bounds
    float wz0 = (z0 >= 0 && z0 < DD) ? (1.0f - fz) : 0.0f;
    float wz1 = (z1 >= 0 && z1 < DD) ? fz          : 0.0f;
    float wy0 = (y0 >= 0 && y0 < HH) ? (1.0f - fy) : 0.0f;
    float wy1 = (y1 >= 0 && y1 < HH) ? fy          : 0.0f;
    float wx0 = (x0 >= 0 && x0 < WW) ? (1.0f - fx) : 0.0f;
    float wx1 = (x1 >= 0 && x1 < WW) ? fx          : 0.0f;

    // clamped indices (value irrelevant when weight is 0)
    int zc0 = min(max(z0, 0), DD - 1);
    int zc1 = min(max(z1, 0), DD - 1);
    int yc0 = min(max(y0, 0), HH - 1);
    int yc1 = min(max(y1, 0), HH - 1);
    int xc0 = min(max(x0, 0), WW - 1);
    int xc1 = min(max(x1, 0), WW - 1);

    const float2* pb = g_pair + (size_t)b * DHW;

    int base00 = (zc0 * HH + yc0) * WW;
    int base01 = (zc0 * HH + yc1) * WW;
    int base10 = (zc1 * HH + yc0) * WW;
    int base11 = (zc1 * HH + yc1) * WW;

    float w000 = wz0 * wy0 * wx0;
    float w001 = wz0 * wy0 * wx1;
    float w010 = wz0 * wy1 * wx0;
    float w011 = wz0 * wy1 * wx1;
    float w100 = wz1 * wy0 * wx0;
    float w101 = wz1 * wy0 * wx1;
    float w110 = wz1 * wy1 * wx0;
    float w111 = wz1 * wy1 * wx1;

    float a0 = 0.0f, a1 = 0.0f;
    float2 v;
    v = __ldg(pb + base00 + xc0); a0 = fmaf(v.x, w000, a0); a1 = fmaf(v.y, w000, a1);
    v = __ldg(pb + base00 + xc1); a0 = fmaf(v.x, w001, a0); a1 = fmaf(v.y, w001, a1);
    v = __ldg(pb + base01 + xc0); a0 = fmaf(v.x, w010, a0); a1 = fmaf(v.y, w010, a1);
    v = __ldg(pb + base01 + xc1); a0 = fmaf(v.x, w011, a0); a1 = fmaf(v.y, w011, a1);
    v = __ldg(pb + base10 + xc0); a0 = fmaf(v.x, w100, a0); a1 = fmaf(v.y, w100, a1);
    v = __ldg(pb + base10 + xc1); a0 = fmaf(v.x, w101, a0); a1 = fmaf(v.y, w101, a1);
    v = __ldg(pb + base11 + xc0); a0 = fmaf(v.x, w110, a0); a1 = fmaf(v.y, w110, a1);
    v = __ldg(pb + base11 + xc1); a0 = fmaf(v.x, w111, a0); a1 = fmaf(v.y, w111, a1);

    float* ob = out + (size_t)b * 2 * DHW;
    ob[s]       = a0;
    ob[s + DHW] = a1;
}

extern "C" void kernel_launch(void* const* d_in, const int* in_sizes, int n_in,
                              void* d_out, int out_size)
{
    const float* x    = (const float*)d_in[0];
    const float* flow = (const float*)d_in[1];
    float* out        = (float*)d_out;

    {
        const int NJ = BB * (DHW / 4);
        const int threads = 256;
        interleave_kernel<<<(NJ + threads - 1) / threads, threads>>>(x);
    }
    {
        const int N = BB * DHW;
        const int threads = 256;
        warp3d_kernel<<<(N + threads - 1) / threads, threads>>>(flow, out);
    }
}